// round 16
// baseline (speedup 1.0000x reference)
#include <cuda_runtime.h>
#include <cuda_bf16.h>
#include <math.h>

#define HW   16384
#define NPIX (8 * 16384)

// ---------------- scratch (device globals: no allocation allowed) ----------
// g_x is NHWC: g_x[(b*HW + hw)*64 + c]
__device__ float g_x[8 * 64 * HW];
__device__ float g_off[8 * 18 * HW];   // planar
__device__ float g_mod[8 * 9 * HW];    // planar

// pre-split weights in smem layout (ROWB=144B pitch, 36 u32/row, pad zeroed)
__device__ unsigned g_wk1[2][2][64 * 36];   // [half][hi/lo][o*36+c]
__device__ unsigned g_wk2[9][2][32 * 36];   // [tap][hi/lo]
__device__ unsigned g_wk3[9][2][64 * 36];   // [tap][hi/lo]

// ---------------- helpers --------------------------------------------------
__device__ __forceinline__ unsigned smem_u32(const void* p) {
    unsigned a;
    asm("{ .reg .u64 t; cvta.to.shared.u64 t, %1; cvt.u32.u64 %0, t; }"
        : "=r"(a) : "l"(p));
    return a;
}
__device__ __forceinline__ unsigned lds32(unsigned a) {
    unsigned v;
    asm("ld.shared.b32 %0, [%1];" : "=r"(v) : "r"(a));
    return v;
}
__device__ __forceinline__ void sts32(unsigned a, unsigned v) {
    asm volatile("st.shared.b32 [%0], %1;" :: "r"(a), "r"(v) : "memory");
}
__device__ __forceinline__ void mma16816(float* d, const unsigned* a,
                                         unsigned b0, unsigned b1) {
    asm volatile(
        "mma.sync.aligned.m16n8k16.row.col.f32.bf16.bf16.f32 "
        "{%0,%1,%2,%3}, {%4,%5,%6,%7}, {%8,%9}, {%0,%1,%2,%3};"
        : "+f"(d[0]), "+f"(d[1]), "+f"(d[2]), "+f"(d[3])
        : "r"(a[0]), "r"(a[1]), "r"(a[2]), "r"(a[3]), "r"(b0), "r"(b1));
}
__device__ __forceinline__ void split_pair(float a, float b,
                                           unsigned& hi, unsigned& lo) {
    __nv_bfloat16 ah = __float2bfloat16(a);
    __nv_bfloat16 bh = __float2bfloat16(b);
    __nv_bfloat16 al = __float2bfloat16(a - __bfloat162float(ah));
    __nv_bfloat16 bl = __float2bfloat16(b - __bfloat162float(bh));
    hi = (unsigned)__bfloat16_as_ushort(ah) | ((unsigned)__bfloat16_as_ushort(bh) << 16);
    lo = (unsigned)__bfloat16_as_ushort(al) | ((unsigned)__bfloat16_as_ushort(bl) << 16);
}

#define ROWB 144

// 128-px tile smem layout
#define SA_HI 0
#define SA_LO 18432
#define SB_HI 36864
#define K1_SB_LO (36864 + 9216)
#define K1_SMEM  (36864 + 18432)      // 55296
#define K2_SB_LO (36864 + 4608)
#define K2_SMEM  (36864 + 9216)       // 46080
#define K3_SB_LO (36864 + 9216)
#define K3_SMEM  (36864 + 18432)      // 55296

// ===========================================================================
// Setup kernel: pre-split all weights into smem-layout global arrays.
// ===========================================================================
__global__ void ksetup(const float* __restrict__ w_fuse,
                       const float* __restrict__ w_off,
                       const float* __restrict__ w_mod,
                       const float* __restrict__ w_reg) {
    int gtid = blockIdx.x * blockDim.x + threadIdx.x;
    int gsz  = gridDim.x * blockDim.x;

    for (int i = gtid; i < 2 * 64 * 36; i += gsz) {
        int half = i / (64 * 36);
        int r = i % (64 * 36);
        int o = r / 36, c = r % 36;
        unsigned hi = 0, lo = 0;
        if (c < 32) {
            int ch = c * 2;
            split_pair(w_fuse[o * 128 + half * 64 + ch],
                       w_fuse[o * 128 + half * 64 + ch + 1], hi, lo);
        }
        g_wk1[half][0][r] = hi;
        g_wk1[half][1][r] = lo;
    }
    for (int i = gtid; i < 9 * 32 * 36; i += gsz) {
        int k = i / (32 * 36);
        int r = i % (32 * 36);
        int o = r / 36, c = r % 36;
        unsigned hi = 0, lo = 0;
        if (c < 32) {
            int ch = c * 2;
            float wa = 0.0f, wb = 0.0f;
            if (o < 18) {
                wa = w_off[((size_t)o * 64 + ch) * 9 + k];
                wb = w_off[((size_t)o * 64 + ch + 1) * 9 + k];
            } else if (o < 27) {
                wa = w_mod[((size_t)(o - 18) * 64 + ch) * 9 + k];
                wb = w_mod[((size_t)(o - 18) * 64 + ch + 1) * 9 + k];
            }
            split_pair(wa, wb, hi, lo);
        }
        g_wk2[k][0][r] = hi;
        g_wk2[k][1][r] = lo;
    }
    for (int i = gtid; i < 9 * 64 * 36; i += gsz) {
        int k = i / (64 * 36);
        int r = i % (64 * 36);
        int o = r / 36, c = r % 36;
        unsigned hi = 0, lo = 0;
        if (c < 32) {
            int ch = c * 2;
            split_pair(w_reg[(size_t)o * 576 + ch * 9 + k],
                       w_reg[(size_t)o * 576 + (ch + 1) * 9 + k], hi, lo);
        }
        g_wk3[k][0][r] = hi;
        g_wk3[k][1][r] = lo;
    }
}

// ===========================================================================
// Kernel 1 (mma.sync): fused 1x1 conv.  128-px tile, 128 thr, 4 CTAs/SM.
// Epilogue writes NHWC g_x (channel pairs -> float2).
// ===========================================================================
__global__ void __launch_bounds__(128, 4)
k1_fuse(const float* __restrict__ x_img,
        const float* __restrict__ x_cont) {
    extern __shared__ char smem[];
    unsigned sb = smem_u32(smem);
    int tid = threadIdx.x;
    int b       = blockIdx.x >> 7;
    int hw_base = (blockIdx.x & 127) << 7;

    int lane = tid & 31, warp = tid >> 5;
    int gid = lane >> 2, tig = lane & 3;

    int px = tid;
    int hw = hw_base + px;

    float d[2][8][4];
#pragma unroll
    for (int mt = 0; mt < 2; mt++)
#pragma unroll
        for (int nt = 0; nt < 8; nt++)
#pragma unroll
            for (int e = 0; e < 4; e++) d[mt][nt][e] = 0.0f;

    unsigned arow_hi = sb + SA_HI + px * ROWB;
    unsigned arow_lo = sb + SA_LO + px * ROWB;

#pragma unroll 1
    for (int half = 0; half < 2; half++) {
        __syncthreads();

        {
            const unsigned* wh = g_wk1[half][0];
            const unsigned* wl = g_wk1[half][1];
#pragma unroll
            for (int idx = tid; idx < 2304; idx += 128) {
                sts32(sb + SB_HI + idx * 4, wh[idx]);
                sts32(sb + K1_SB_LO + idx * 4, wl[idx]);
            }
        }

        const float* xs = (half == 0 ? x_img : x_cont) + (size_t)b * 64 * HW + hw;
#pragma unroll 1
        for (int c0 = 0; c0 < 64; c0 += 8) {
            float v[8];
#pragma unroll
            for (int u = 0; u < 8; u++) v[u] = xs[(size_t)(c0 + u) * HW];
#pragma unroll
            for (int p2 = 0; p2 < 4; p2++) {
                unsigned hi, lo;
                split_pair(v[2 * p2], v[2 * p2 + 1], hi, lo);
                sts32(arow_hi + (c0 + 2 * p2) * 2, hi);
                sts32(arow_lo + (c0 + 2 * p2) * 2, lo);
            }
        }

        __syncthreads();

#pragma unroll
        for (int ks = 0; ks < 4; ks++) {
            unsigned kbyte = (unsigned)(ks * 16 + tig * 2) * 2;
            unsigned ahi[2][4], alo[2][4];
#pragma unroll
            for (int mt = 0; mt < 2; mt++) {
                unsigned r0 = warp * 32 + mt * 16 + gid;
                unsigned bh = sb + SA_HI + r0 * ROWB + kbyte;
                unsigned bl = sb + SA_LO + r0 * ROWB + kbyte;
                ahi[mt][0] = lds32(bh);
                ahi[mt][1] = lds32(bh + 8 * ROWB);
                ahi[mt][2] = lds32(bh + 16);
                ahi[mt][3] = lds32(bh + 8 * ROWB + 16);
                alo[mt][0] = lds32(bl);
                alo[mt][1] = lds32(bl + 8 * ROWB);
                alo[mt][2] = lds32(bl + 16);
                alo[mt][3] = lds32(bl + 8 * ROWB + 16);
            }
#pragma unroll
            for (int nt = 0; nt < 8; nt++) {
                unsigned nrow = nt * 8 + gid;
                unsigned bbh = sb + SB_HI + nrow * ROWB + kbyte;
                unsigned bbl = sb + K1_SB_LO + nrow * ROWB + kbyte;
                unsigned bh0 = lds32(bbh), bh1 = lds32(bbh + 16);
                unsigned bl0 = lds32(bbl), bl1 = lds32(bbl + 16);
#pragma unroll
                for (int mt = 0; mt < 2; mt++) {
                    mma16816(d[mt][nt], ahi[mt], bh0, bh1);
                    mma16816(d[mt][nt], ahi[mt], bl0, bl1);
                    mma16816(d[mt][nt], alo[mt], bh0, bh1);
                }
            }
        }
    }

    // ---- epilogue -> NHWC g_x (channel pairs = float2) ----
#pragma unroll
    for (int mt = 0; mt < 2; mt++) {
#pragma unroll
        for (int nt = 0; nt < 8; nt++) {
            int px0 = warp * 32 + mt * 16 + gid;
            int o0  = nt * 8 + tig * 2;
            float* p0 = g_x + ((size_t)(b * HW + hw_base + px0)) * 64 + o0;
            float* p1 = g_x + ((size_t)(b * HW + hw_base + px0 + 8)) * 64 + o0;
            *(float2*)p0 = make_float2(d[mt][nt][0], d[mt][nt][1]);
            *(float2*)p1 = make_float2(d[mt][nt][2], d[mt][nt][3]);
        }
    }
}

// ===========================================================================
// Kernel 2 (mma.sync): 3x3 conv -> offsets/mod.  NHWC reads (float4 x16).
// ===========================================================================
__global__ void __launch_bounds__(128, 4)
k2_offmod(const float* __restrict__ b_off,
          const float* __restrict__ b_mod) {
    extern __shared__ char smem[];
    unsigned sb = smem_u32(smem);
    int tid = threadIdx.x;
    int b       = blockIdx.x >> 7;
    int hw_base = (blockIdx.x & 127) << 7;

    int lane = tid & 31, warp = tid >> 5;
    int gid = lane >> 2, tig = lane & 3;

    int px = tid;
    int hw = hw_base + px;
    int h  = hw >> 7;
    int w  = hw & 127;

    const float* xs = g_x + (size_t)b * HW * 64;

    float d[2][4][4];
#pragma unroll
    for (int mt = 0; mt < 2; mt++)
#pragma unroll
        for (int nt = 0; nt < 4; nt++)
#pragma unroll
            for (int e = 0; e < 4; e++) d[mt][nt][e] = 0.0f;

    unsigned arow_hi = sb + SA_HI + px * ROWB;
    unsigned arow_lo = sb + SA_LO + px * ROWB;

#pragma unroll 1
    for (int k = 0; k < 9; k++) {
        __syncthreads();

        {
            const unsigned* wh = g_wk2[k][0];
            const unsigned* wl = g_wk2[k][1];
#pragma unroll
            for (int idx = tid; idx < 1152; idx += 128) {
                sts32(sb + SB_HI + idx * 4, wh[idx]);
                sts32(sb + K2_SB_LO + idx * 4, wl[idx]);
            }
        }

        {
            int ty = k / 3 - 1, tx = k % 3 - 1;
            int yy = h + ty, xx = w + tx;
            bool ok = ((unsigned)yy < 128u) && ((unsigned)xx < 128u);
            const float* xp = xs + (size_t)(ok ? (yy * 128 + xx) : 0) * 64;
#pragma unroll 2
            for (int c0 = 0; c0 < 64; c0 += 8) {
                float4 va = ok ? *(const float4*)(xp + c0)
                               : make_float4(0.f, 0.f, 0.f, 0.f);
                float4 vb = ok ? *(const float4*)(xp + c0 + 4)
                               : make_float4(0.f, 0.f, 0.f, 0.f);
                unsigned hi, lo;
                split_pair(va.x, va.y, hi, lo);
                sts32(arow_hi + c0 * 2, hi);
                sts32(arow_lo + c0 * 2, lo);
                split_pair(va.z, va.w, hi, lo);
                sts32(arow_hi + c0 * 2 + 4, hi);
                sts32(arow_lo + c0 * 2 + 4, lo);
                split_pair(vb.x, vb.y, hi, lo);
                sts32(arow_hi + c0 * 2 + 8, hi);
                sts32(arow_lo + c0 * 2 + 8, lo);
                split_pair(vb.z, vb.w, hi, lo);
                sts32(arow_hi + c0 * 2 + 12, hi);
                sts32(arow_lo + c0 * 2 + 12, lo);
            }
        }

        __syncthreads();

#pragma unroll
        for (int ks = 0; ks < 4; ks++) {
            unsigned kbyte = (unsigned)(ks * 16 + tig * 2) * 2;
            unsigned ahi[2][4], alo[2][4];
#pragma unroll
            for (int mt = 0; mt < 2; mt++) {
                unsigned r0 = warp * 32 + mt * 16 + gid;
                unsigned bh = sb + SA_HI + r0 * ROWB + kbyte;
                unsigned bl = sb + SA_LO + r0 * ROWB + kbyte;
                ahi[mt][0] = lds32(bh);
                ahi[mt][1] = lds32(bh + 8 * ROWB);
                ahi[mt][2] = lds32(bh + 16);
                ahi[mt][3] = lds32(bh + 8 * ROWB + 16);
                alo[mt][0] = lds32(bl);
                alo[mt][1] = lds32(bl + 8 * ROWB);
                alo[mt][2] = lds32(bl + 16);
                alo[mt][3] = lds32(bl + 8 * ROWB + 16);
            }
#pragma unroll
            for (int nt = 0; nt < 4; nt++) {
                unsigned nrow = nt * 8 + gid;
                unsigned bbh = sb + SB_HI + nrow * ROWB + kbyte;
                unsigned bbl = sb + K2_SB_LO + nrow * ROWB + kbyte;
                unsigned bh0 = lds32(bbh), bh1 = lds32(bbh + 16);
                unsigned bl0 = lds32(bbl), bl1 = lds32(bbl + 16);
#pragma unroll
                for (int mt = 0; mt < 2; mt++) {
                    mma16816(d[mt][nt], ahi[mt], bh0, bh1);
                    mma16816(d[mt][nt], ahi[mt], bl0, bl1);
                    mma16816(d[mt][nt], alo[mt], bh0, bh1);
                }
            }
        }
    }

#pragma unroll
    for (int mt = 0; mt < 2; mt++) {
#pragma unroll
        for (int nt = 0; nt < 4; nt++) {
#pragma unroll
            for (int e = 0; e < 4; e++) {
                int o   = nt * 8 + tig * 2 + (e & 1);
                int px0 = warp * 32 + mt * 16 + gid + ((e >> 1) ? 8 : 0);
                float val = d[mt][nt][e];
                if (o < 18) {
                    g_off[((size_t)b * 18 + o) * HW + hw_base + px0]
                        = val + b_off[o];
                } else if (o < 27) {
                    float m = val + b_mod[o - 18];
                    g_mod[((size_t)b * 9 + (o - 18)) * HW + hw_base + px0]
                        = 2.0f / (1.0f + __expf(-m));
                }
            }
        }
    }
}

// ===========================================================================
// Kernel 3 (mma.sync): deformable sample + GEMM.  128-px tile, 4 CTAs/SM.
// NHWC sampling: each corner = 16 float4 loads (was 64 scalar).
// ===========================================================================
__global__ void __launch_bounds__(128, 4)
k3_deform(float* __restrict__ out) {
    extern __shared__ char smem[];
    unsigned sb = smem_u32(smem);
    int tid = threadIdx.x;
    int b       = blockIdx.x >> 7;
    int hw_base = (blockIdx.x & 127) << 7;

    int lane = tid & 31, warp = tid >> 5;
    int gid = lane >> 2, tig = lane & 3;

    int px = tid;
    int hw = hw_base + px;
    int h  = hw >> 7;
    int w  = hw & 127;

    const float* xb   = g_x   + (size_t)b * HW * 64;
    const float* offp = g_off + (size_t)b * 18 * HW + hw;
    const float* modp = g_mod + (size_t)b * 9 * HW + hw;

    float d[2][8][4];
#pragma unroll
    for (int mt = 0; mt < 2; mt++)
#pragma unroll
        for (int nt = 0; nt < 8; nt++)
#pragma unroll
            for (int e = 0; e < 4; e++) d[mt][nt][e] = 0.0f;

    unsigned arow_hi = sb + SA_HI + px * ROWB;
    unsigned arow_lo = sb + SA_LO + px * ROWB;

    float dy = offp[0];
    float dx = offp[(size_t)HW];
    float mk = modp[0];

#pragma unroll 1
    for (int k = 0; k < 9; k++) {
        __syncthreads();

        {
            const unsigned* wh = g_wk3[k][0];
            const unsigned* wl = g_wk3[k][1];
#pragma unroll
            for (int idx = tid; idx < 2304; idx += 128) {
                sts32(sb + SB_HI + idx * 4, wh[idx]);
                sts32(sb + K3_SB_LO + idx * 4, wl[idx]);
            }
        }

        // ---- bilinear params + next-tap prefetch ----
        int ky = k / 3, kx = k % 3;
        float py  = dy + (float)(h - 1 + ky);
        float pxx = dx + (float)(w - 1 + kx);
        float y0f = floorf(py), x0f = floorf(pxx);
        float wy1 = py - y0f, wy0 = 1.0f - wy1;
        float wx1 = pxx - x0f, wx0 = 1.0f - wx1;
        int y0 = (int)y0f, x0 = (int)x0f;
        int y1 = y0 + 1,   x1 = x0 + 1;
        bool vy0 = (unsigned)y0 < 128u, vy1 = (unsigned)y1 < 128u;
        bool vx0 = (unsigned)x0 < 128u, vx1 = (unsigned)x1 < 128u;
        float w00 = (vy0 && vx0) ? wy0 * wx0 * mk : 0.0f;
        float w01 = (vy0 && vx1) ? wy0 * wx1 * mk : 0.0f;
        float w10 = (vy1 && vx0) ? wy1 * wx0 * mk : 0.0f;
        float w11 = (vy1 && vx1) ? wy1 * wx1 * mk : 0.0f;
        int y0c = min(max(y0, 0), 127), y1c = min(max(y1, 0), 127);
        int x0c = min(max(x0, 0), 127), x1c = min(max(x1, 0), 127);
        const float* p00 = xb + (size_t)(y0c * 128 + x0c) * 64;
        const float* p01 = xb + (size_t)(y0c * 128 + x1c) * 64;
        const float* p10 = xb + (size_t)(y1c * 128 + x0c) * 64;
        const float* p11 = xb + (size_t)(y1c * 128 + x1c) * 64;

        if (k < 8) {
            dy = offp[(size_t)(2 * k + 2) * HW];
            dx = offp[(size_t)(2 * k + 3) * HW];
            mk = modp[(size_t)(k + 1) * HW];
        }

        // ---- sample 64 channels via float4 corners, split + STS ----
#pragma unroll 2
        for (int c0 = 0; c0 < 64; c0 += 4) {
            float4 v00 = *(const float4*)(p00 + c0);
            float4 v01 = *(const float4*)(p01 + c0);
            float4 v10 = *(const float4*)(p10 + c0);
            float4 v11 = *(const float4*)(p11 + c0);
            float s0 = fmaf(v11.x, w11, fmaf(v10.x, w10,
                       fmaf(v01.x, w01, v00.x * w00)));
            float s1 = fmaf(v11.y, w11, fmaf(v10.y, w10,
                       fmaf(v01.y, w01, v00.y * w00)));
            float s2 = fmaf(v11.z, w11, fmaf(v10.z, w10,
                       fmaf(v01.z, w01, v00.z * w00)));
            float s3 = fmaf(v11.w, w11, fmaf(v10.w, w10,
                       fmaf(v01.w, w01, v00.w * w00)));
            unsigned hi, lo;
            split_pair(s0, s1, hi, lo);
            sts32(arow_hi + c0 * 2, hi);
            sts32(arow_lo + c0 * 2, lo);
            split_pair(s2, s3, hi, lo);
            sts32(arow_hi + c0 * 2 + 4, hi);
            sts32(arow_lo + c0 * 2 + 4, lo);
        }

        __syncthreads();

        // ---- warp GEMM: 32 px x 64 out, K=64, 3 terms ----
#pragma unroll
        for (int ks = 0; ks < 4; ks++) {
            unsigned kbyte = (unsigned)(ks * 16 + tig * 2) * 2;
            unsigned ahi[2][4], alo[2][4];
#pragma unroll
            for (int mt = 0; mt < 2; mt++) {
                unsigned r0 = warp * 32 + mt * 16 + gid;
                unsigned bh = sb + SA_HI + r0 * ROWB + kbyte;
                unsigned bl = sb + SA_LO + r0 * ROWB + kbyte;
                ahi[mt][0] = lds32(bh);
                ahi[mt][1] = lds32(bh + 8 * ROWB);
                ahi[mt][2] = lds32(bh + 16);
                ahi[mt][3] = lds32(bh + 8 * ROWB + 16);
                alo[mt][0] = lds32(bl);
                alo[mt][1] = lds32(bl + 8 * ROWB);
                alo[mt][2] = lds32(bl + 16);
                alo[mt][3] = lds32(bl + 8 * ROWB + 16);
            }
#pragma unroll
            for (int nt = 0; nt < 8; nt++) {
                unsigned nrow = nt * 8 + gid;
                unsigned bbh = sb + SB_HI + nrow * ROWB + kbyte;
                unsigned bbl = sb + K3_SB_LO + nrow * ROWB + kbyte;
                unsigned bh0 = lds32(bbh), bh1 = lds32(bbh + 16);
                unsigned bl0 = lds32(bbl), bl1 = lds32(bbl + 16);
#pragma unroll
                for (int mt = 0; mt < 2; mt++) {
                    mma16816(d[mt][nt], ahi[mt], bh0, bh1);
                    mma16816(d[mt][nt], ahi[mt], bl0, bl1);
                    mma16816(d[mt][nt], alo[mt], bh0, bh1);
                }
            }
        }
    }

#pragma unroll
    for (int mt = 0; mt < 2; mt++) {
#pragma unroll
        for (int nt = 0; nt < 8; nt++) {
            int px0 = warp * 32 + mt * 16 + gid;
            int o0  = nt * 8 + tig * 2;
            float* op = out + ((size_t)b * 64 + o0) * HW + hw_base;
            op[px0]           = d[mt][nt][0];
            op[HW + px0]      = d[mt][nt][1];
            op[px0 + 8]       = d[mt][nt][2];
            op[HW + px0 + 8]  = d[mt][nt][3];
        }
    }
}

// ===========================================================================
extern "C" void kernel_launch(void* const* d_in, const int* in_sizes, int n_in,
                              void* d_out, int out_size) {
    const float* x_img  = (const float*)d_in[0];
    const float* x_cont = (const float*)d_in[1];
    const float* w_fuse = (const float*)d_in[2];
    const float* w_off  = (const float*)d_in[3];
    const float* b_off  = (const float*)d_in[4];
    const float* w_mod  = (const float*)d_in[5];
    const float* b_mod  = (const float*)d_in[6];
    const float* w_reg  = (const float*)d_in[7];
    float* out = (float*)d_out;

    cudaFuncSetAttribute(k1_fuse,
                         cudaFuncAttributeMaxDynamicSharedMemorySize, K1_SMEM);
    cudaFuncSetAttribute(k2_offmod,
                         cudaFuncAttributeMaxDynamicSharedMemorySize, K2_SMEM);
    cudaFuncSetAttribute(k3_deform,
                         cudaFuncAttributeMaxDynamicSharedMemorySize, K3_SMEM);

    ksetup<<<128, 256>>>(w_fuse, w_off, w_mod, w_reg);
    // all: 1024 blocks x 128 thr; CTA = 128-px tile
    k1_fuse<<<1024, 128, K1_SMEM>>>(x_img, x_cont);
    k2_offmod<<<1024, 128, K2_SMEM>>>(b_off, b_mod);
    k3_deform<<<1024, 128, K3_SMEM>>>(out);
}

// round 17
// speedup vs baseline: 1.6646x; 1.6646x over previous
#include <cuda_runtime.h>
#include <cuda_bf16.h>
#include <math.h>

#define HW   16384
#define NPIX (8 * 16384)

// ---------------- scratch (device globals: no allocation allowed) ----------
__device__ float g_x[8 * 64 * HW];     // fused 1x1 conv output (NCHW)
__device__ float g_off[8 * 18 * HW];   // raw offset conv + bias
__device__ float g_mod[8 * 9 * HW];    // 2*sigmoid(conv + bias)

// pre-split weights in smem layout (ROWB=144B pitch, 36 u32/row, pad zeroed)
__device__ unsigned g_wk1[2][2][64 * 36];   // [half][hi/lo][o*36+c]
__device__ unsigned g_wk2[9][2][32 * 36];   // [tap][hi/lo]
__device__ unsigned g_wk3[9][2][64 * 36];   // [tap][hi/lo]

// ---------------- helpers --------------------------------------------------
__device__ __forceinline__ unsigned smem_u32(const void* p) {
    unsigned a;
    asm("{ .reg .u64 t; cvta.to.shared.u64 t, %1; cvt.u32.u64 %0, t; }"
        : "=r"(a) : "l"(p));
    return a;
}
__device__ __forceinline__ void sts32(unsigned a, unsigned v) {
    asm volatile("st.shared.b32 [%0], %1;" :: "r"(a), "r"(v) : "memory");
}
__device__ __forceinline__ void ldsm_x4(unsigned* r, unsigned addr) {
    asm volatile("ldmatrix.sync.aligned.m8n8.x4.shared.b16 {%0,%1,%2,%3}, [%4];"
        : "=r"(r[0]), "=r"(r[1]), "=r"(r[2]), "=r"(r[3]) : "r"(addr));
}
__device__ __forceinline__ void mma16816(float* d, const unsigned* a,
                                         unsigned b0, unsigned b1) {
    asm volatile(
        "mma.sync.aligned.m16n8k16.row.col.f32.bf16.bf16.f32 "
        "{%0,%1,%2,%3}, {%4,%5,%6,%7}, {%8,%9}, {%0,%1,%2,%3};"
        : "+f"(d[0]), "+f"(d[1]), "+f"(d[2]), "+f"(d[3])
        : "r"(a[0]), "r"(a[1]), "r"(a[2]), "r"(a[3]), "r"(b0), "r"(b1));
}
__device__ __forceinline__ void split_pair(float a, float b,
                                           unsigned& hi, unsigned& lo) {
    __nv_bfloat16 ah = __float2bfloat16(a);
    __nv_bfloat16 bh = __float2bfloat16(b);
    __nv_bfloat16 al = __float2bfloat16(a - __bfloat162float(ah));
    __nv_bfloat16 bl = __float2bfloat16(b - __bfloat162float(bh));
    hi = (unsigned)__bfloat16_as_ushort(ah) | ((unsigned)__bfloat16_as_ushort(bh) << 16);
    lo = (unsigned)__bfloat16_as_ushort(al) | ((unsigned)__bfloat16_as_ushort(bl) << 16);
}

#define ROWB 144

// 128-px tile smem layout
#define SA_HI 0
#define SA_LO 18432
#define SB_HI 36864
#define K1_SB_LO (36864 + 9216)
#define K1_SMEM  (36864 + 18432)      // 55296
#define K2_SB_LO (36864 + 4608)
#define K2_SMEM  (36864 + 9216)       // 46080
#define K3_SB_LO (36864 + 9216)
#define K3_SMEM  (36864 + 18432)      // 55296

// Per-thread ldmatrix address offsets:
// A x4 (16x16 tile): row = mbase + (lane&15), col16B = (lane>>4)
// B x4 (two n8k16):  row = 16p + (lane&7) + ((lane>>4)<<3), col16B = (lane>>3)&1
#define A_FRAG_OFF(lane) ((unsigned)(((lane) & 15) * ROWB + (((lane) >> 4) << 4)))
#define B_FRAG_OFF(lane) ((unsigned)((((lane) & 7) + (((lane) >> 4) << 3)) * ROWB \
                                     + ((((lane) >> 3) & 1) << 4)))

// ===========================================================================
// Setup kernel: pre-split all weights into smem-layout global arrays.
// ===========================================================================
__global__ void ksetup(const float* __restrict__ w_fuse,
                       const float* __restrict__ w_off,
                       const float* __restrict__ w_mod,
                       const float* __restrict__ w_reg) {
    int gtid = blockIdx.x * blockDim.x + threadIdx.x;
    int gsz  = gridDim.x * blockDim.x;

    for (int i = gtid; i < 2 * 64 * 36; i += gsz) {
        int half = i / (64 * 36);
        int r = i % (64 * 36);
        int o = r / 36, c = r % 36;
        unsigned hi = 0, lo = 0;
        if (c < 32) {
            int ch = c * 2;
            split_pair(w_fuse[o * 128 + half * 64 + ch],
                       w_fuse[o * 128 + half * 64 + ch + 1], hi, lo);
        }
        g_wk1[half][0][r] = hi;
        g_wk1[half][1][r] = lo;
    }
    for (int i = gtid; i < 9 * 32 * 36; i += gsz) {
        int k = i / (32 * 36);
        int r = i % (32 * 36);
        int o = r / 36, c = r % 36;
        unsigned hi = 0, lo = 0;
        if (c < 32) {
            int ch = c * 2;
            float wa = 0.0f, wb = 0.0f;
            if (o < 18) {
                wa = w_off[((size_t)o * 64 + ch) * 9 + k];
                wb = w_off[((size_t)o * 64 + ch + 1) * 9 + k];
            } else if (o < 27) {
                wa = w_mod[((size_t)(o - 18) * 64 + ch) * 9 + k];
                wb = w_mod[((size_t)(o - 18) * 64 + ch + 1) * 9 + k];
            }
            split_pair(wa, wb, hi, lo);
        }
        g_wk2[k][0][r] = hi;
        g_wk2[k][1][r] = lo;
    }
    for (int i = gtid; i < 9 * 64 * 36; i += gsz) {
        int k = i / (64 * 36);
        int r = i % (64 * 36);
        int o = r / 36, c = r % 36;
        unsigned hi = 0, lo = 0;
        if (c < 32) {
            int ch = c * 2;
            split_pair(w_reg[(size_t)o * 576 + ch * 9 + k],
                       w_reg[(size_t)o * 576 + (ch + 1) * 9 + k], hi, lo);
        }
        g_wk3[k][0][r] = hi;
        g_wk3[k][1][r] = lo;
    }
}

// ===========================================================================
// Kernel 1 (mma.sync + ldmatrix): fused 1x1 conv.  128-px tile, 4 CTAs/SM.
// ===========================================================================
__global__ void __launch_bounds__(128, 4)
k1_fuse(const float* __restrict__ x_img,
        const float* __restrict__ x_cont) {
    extern __shared__ char smem[];
    unsigned sb = smem_u32(smem);
    int tid = threadIdx.x;
    int b       = blockIdx.x >> 7;
    int hw_base = (blockIdx.x & 127) << 7;

    int lane = tid & 31, warp = tid >> 5;
    int gid = lane >> 2, tig = lane & 3;

    int px = tid;
    int hw = hw_base + px;

    float d[2][8][4];
#pragma unroll
    for (int mt = 0; mt < 2; mt++)
#pragma unroll
        for (int nt = 0; nt < 8; nt++)
#pragma unroll
            for (int e = 0; e < 4; e++) d[mt][nt][e] = 0.0f;

    unsigned arow_hi = sb + SA_HI + px * ROWB;
    unsigned arow_lo = sb + SA_LO + px * ROWB;
    unsigned afrag = warp * 32 * ROWB + A_FRAG_OFF(lane);
    unsigned bfrag = B_FRAG_OFF(lane);

#pragma unroll 1
    for (int half = 0; half < 2; half++) {
        __syncthreads();

        {
            const unsigned* wh = g_wk1[half][0];
            const unsigned* wl = g_wk1[half][1];
#pragma unroll
            for (int idx = tid; idx < 2304; idx += 128) {
                sts32(sb + SB_HI + idx * 4, wh[idx]);
                sts32(sb + K1_SB_LO + idx * 4, wl[idx]);
            }
        }

        const float* xs = (half == 0 ? x_img : x_cont) + (size_t)b * 64 * HW + hw;
#pragma unroll 1
        for (int c0 = 0; c0 < 64; c0 += 8) {
            float v[8];
#pragma unroll
            for (int u = 0; u < 8; u++) v[u] = xs[(size_t)(c0 + u) * HW];
#pragma unroll
            for (int p2 = 0; p2 < 4; p2++) {
                unsigned hi, lo;
                split_pair(v[2 * p2], v[2 * p2 + 1], hi, lo);
                sts32(arow_hi + (c0 + 2 * p2) * 2, hi);
                sts32(arow_lo + (c0 + 2 * p2) * 2, lo);
            }
        }

        __syncthreads();

#pragma unroll
        for (int ks = 0; ks < 4; ks++) {
            unsigned kb = ks * 32;
            unsigned ahi[2][4], alo[2][4];
#pragma unroll
            for (int mt = 0; mt < 2; mt++) {
                ldsm_x4(ahi[mt], sb + SA_HI + afrag + mt * 16 * ROWB + kb);
                ldsm_x4(alo[mt], sb + SA_LO + afrag + mt * 16 * ROWB + kb);
            }
#pragma unroll
            for (int p = 0; p < 4; p++) {
                unsigned bh4[4], bl4[4];
                ldsm_x4(bh4, sb + SB_HI + p * 16 * ROWB + bfrag + kb);
                ldsm_x4(bl4, sb + K1_SB_LO + p * 16 * ROWB + bfrag + kb);
#pragma unroll
                for (int mt = 0; mt < 2; mt++) {
                    mma16816(d[mt][2 * p],     ahi[mt], bh4[0], bh4[1]);
                    mma16816(d[mt][2 * p],     ahi[mt], bl4[0], bl4[1]);
                    mma16816(d[mt][2 * p],     alo[mt], bh4[0], bh4[1]);
                    mma16816(d[mt][2 * p + 1], ahi[mt], bh4[2], bh4[3]);
                    mma16816(d[mt][2 * p + 1], ahi[mt], bl4[2], bl4[3]);
                    mma16816(d[mt][2 * p + 1], alo[mt], bh4[2], bh4[3]);
                }
            }
        }
    }

#pragma unroll
    for (int mt = 0; mt < 2; mt++) {
#pragma unroll
        for (int nt = 0; nt < 8; nt++) {
            int px0 = warp * 32 + mt * 16 + gid;
            int o0  = nt * 8 + tig * 2;
            float* op = g_x + ((size_t)b * 64 + o0) * HW + hw_base;
            op[px0]           = d[mt][nt][0];
            op[HW + px0]      = d[mt][nt][1];
            op[px0 + 8]       = d[mt][nt][2];
            op[HW + px0 + 8]  = d[mt][nt][3];
        }
    }
}

// ===========================================================================
// Kernel 2 (mma.sync + ldmatrix): 3x3 conv -> offsets/mod.
// ===========================================================================
__global__ void __launch_bounds__(128, 4)
k2_offmod(const float* __restrict__ b_off,
          const float* __restrict__ b_mod) {
    extern __shared__ char smem[];
    unsigned sb = smem_u32(smem);
    int tid = threadIdx.x;
    int b       = blockIdx.x >> 7;
    int hw_base = (blockIdx.x & 127) << 7;

    int lane = tid & 31, warp = tid >> 5;
    int gid = lane >> 2, tig = lane & 3;

    int px = tid;
    int hw = hw_base + px;
    int h  = hw >> 7;
    int w  = hw & 127;

    const float* xs = g_x + (size_t)b * 64 * HW;

    float d[2][4][4];
#pragma unroll
    for (int mt = 0; mt < 2; mt++)
#pragma unroll
        for (int nt = 0; nt < 4; nt++)
#pragma unroll
            for (int e = 0; e < 4; e++) d[mt][nt][e] = 0.0f;

    unsigned arow_hi = sb + SA_HI + px * ROWB;
    unsigned arow_lo = sb + SA_LO + px * ROWB;
    unsigned afrag = warp * 32 * ROWB + A_FRAG_OFF(lane);
    unsigned bfrag = B_FRAG_OFF(lane);

#pragma unroll 1
    for (int k = 0; k < 9; k++) {
        __syncthreads();

        {
            const unsigned* wh = g_wk2[k][0];
            const unsigned* wl = g_wk2[k][1];
#pragma unroll
            for (int idx = tid; idx < 1152; idx += 128) {
                sts32(sb + SB_HI + idx * 4, wh[idx]);
                sts32(sb + K2_SB_LO + idx * 4, wl[idx]);
            }
        }

        {
            int ty = k / 3 - 1, tx = k % 3 - 1;
            int yy = h + ty, xx = w + tx;
            bool ok = ((unsigned)yy < 128u) && ((unsigned)xx < 128u);
            int addr = ok ? yy * 128 + xx : 0;
#pragma unroll 1
            for (int c0 = 0; c0 < 64; c0 += 8) {
                float v[8];
#pragma unroll
                for (int u = 0; u < 8; u++)
                    v[u] = ok ? xs[(size_t)(c0 + u) * HW + addr] : 0.0f;
#pragma unroll
                for (int p2 = 0; p2 < 4; p2++) {
                    unsigned hi, lo;
                    split_pair(v[2 * p2], v[2 * p2 + 1], hi, lo);
                    sts32(arow_hi + (c0 + 2 * p2) * 2, hi);
                    sts32(arow_lo + (c0 + 2 * p2) * 2, lo);
                }
            }
        }

        __syncthreads();

#pragma unroll
        for (int ks = 0; ks < 4; ks++) {
            unsigned kb = ks * 32;
            unsigned ahi[2][4], alo[2][4];
#pragma unroll
            for (int mt = 0; mt < 2; mt++) {
                ldsm_x4(ahi[mt], sb + SA_HI + afrag + mt * 16 * ROWB + kb);
                ldsm_x4(alo[mt], sb + SA_LO + afrag + mt * 16 * ROWB + kb);
            }
#pragma unroll
            for (int p = 0; p < 2; p++) {
                unsigned bh4[4], bl4[4];
                ldsm_x4(bh4, sb + SB_HI + p * 16 * ROWB + bfrag + kb);
                ldsm_x4(bl4, sb + K2_SB_LO + p * 16 * ROWB + bfrag + kb);
#pragma unroll
                for (int mt = 0; mt < 2; mt++) {
                    mma16816(d[mt][2 * p],     ahi[mt], bh4[0], bh4[1]);
                    mma16816(d[mt][2 * p],     ahi[mt], bl4[0], bl4[1]);
                    mma16816(d[mt][2 * p],     alo[mt], bh4[0], bh4[1]);
                    mma16816(d[mt][2 * p + 1], ahi[mt], bh4[2], bh4[3]);
                    mma16816(d[mt][2 * p + 1], ahi[mt], bl4[2], bl4[3]);
                    mma16816(d[mt][2 * p + 1], alo[mt], bh4[2], bh4[3]);
                }
            }
        }
    }

#pragma unroll
    for (int mt = 0; mt < 2; mt++) {
#pragma unroll
        for (int nt = 0; nt < 4; nt++) {
#pragma unroll
            for (int e = 0; e < 4; e++) {
                int o   = nt * 8 + tig * 2 + (e & 1);
                int px0 = warp * 32 + mt * 16 + gid + ((e >> 1) ? 8 : 0);
                float val = d[mt][nt][e];
                if (o < 18) {
                    g_off[((size_t)b * 18 + o) * HW + hw_base + px0]
                        = val + b_off[o];
                } else if (o < 27) {
                    float m = val + b_mod[o - 18];
                    g_mod[((size_t)b * 9 + (o - 18)) * HW + hw_base + px0]
                        = 2.0f / (1.0f + __expf(-m));
                }
            }
        }
    }
}

// ===========================================================================
// Kernel 3 (mma.sync + ldmatrix): deformable sample + GEMM.  128-px tile.
// ===========================================================================
__global__ void __launch_bounds__(128, 4)
k3_deform(float* __restrict__ out) {
    extern __shared__ char smem[];
    unsigned sb = smem_u32(smem);
    int tid = threadIdx.x;
    int b       = blockIdx.x >> 7;
    int hw_base = (blockIdx.x & 127) << 7;

    int lane = tid & 31, warp = tid >> 5;
    int gid = lane >> 2, tig = lane & 3;

    int px = tid;
    int hw = hw_base + px;
    int h  = hw >> 7;
    int w  = hw & 127;

    const float* xb   = g_x   + (size_t)b * 64 * HW;
    const float* offp = g_off + (size_t)b * 18 * HW + hw;
    const float* modp = g_mod + (size_t)b * 9 * HW + hw;

    float d[2][8][4];
#pragma unroll
    for (int mt = 0; mt < 2; mt++)
#pragma unroll
        for (int nt = 0; nt < 8; nt++)
#pragma unroll
            for (int e = 0; e < 4; e++) d[mt][nt][e] = 0.0f;

    unsigned arow_hi = sb + SA_HI + px * ROWB;
    unsigned arow_lo = sb + SA_LO + px * ROWB;
    unsigned afrag = warp * 32 * ROWB + A_FRAG_OFF(lane);
    unsigned bfrag = B_FRAG_OFF(lane);

    float dy = offp[0];
    float dx = offp[(size_t)HW];
    float mk = modp[0];

#pragma unroll 1
    for (int k = 0; k < 9; k++) {
        __syncthreads();

        {
            const unsigned* wh = g_wk3[k][0];
            const unsigned* wl = g_wk3[k][1];
#pragma unroll
            for (int idx = tid; idx < 2304; idx += 128) {
                sts32(sb + SB_HI + idx * 4, wh[idx]);
                sts32(sb + K3_SB_LO + idx * 4, wl[idx]);
            }
        }

        // ---- bilinear params (prefetched) + next-tap prefetch ----
        int ky = k / 3, kx = k % 3;
        float py  = dy + (float)(h - 1 + ky);
        float pxx = dx + (float)(w - 1 + kx);
        float y0f = floorf(py), x0f = floorf(pxx);
        float wy1 = py - y0f, wy0 = 1.0f - wy1;
        float wx1 = pxx - x0f, wx0 = 1.0f - wx1;
        int y0 = (int)y0f, x0 = (int)x0f;
        int y1 = y0 + 1,   x1 = x0 + 1;
        bool vy0 = (unsigned)y0 < 128u, vy1 = (unsigned)y1 < 128u;
        bool vx0 = (unsigned)x0 < 128u, vx1 = (unsigned)x1 < 128u;
        float w00 = (vy0 && vx0) ? wy0 * wx0 * mk : 0.0f;
        float w01 = (vy0 && vx1) ? wy0 * wx1 * mk : 0.0f;
        float w10 = (vy1 && vx0) ? wy1 * wx0 * mk : 0.0f;
        float w11 = (vy1 && vx1) ? wy1 * wx1 * mk : 0.0f;
        int y0c = min(max(y0, 0), 127), y1c = min(max(y1, 0), 127);
        int x0c = min(max(x0, 0), 127), x1c = min(max(x1, 0), 127);
        int a00 = y0c * 128 + x0c;
        int a01 = y0c * 128 + x1c;
        int a10 = y1c * 128 + x0c;
        int a11 = y1c * 128 + x1c;

        if (k < 8) {
            dy = offp[(size_t)(2 * k + 2) * HW];
            dx = offp[(size_t)(2 * k + 3) * HW];
            mk = modp[(size_t)(k + 1) * HW];
        }

        // ---- sample 64 channels, split + STS ----
#pragma unroll 1
        for (int c0 = 0; c0 < 64; c0 += 4) {
            float v[16];
#pragma unroll
            for (int u = 0; u < 4; u++) {
                const float* pi = xb + (size_t)(c0 + u) * HW;
                v[4 * u + 0] = pi[a00];
                v[4 * u + 1] = pi[a01];
                v[4 * u + 2] = pi[a10];
                v[4 * u + 3] = pi[a11];
            }
            float s[4];
#pragma unroll
            for (int u = 0; u < 4; u++) {
                float sv = v[4 * u + 0] * w00;
                sv = fmaf(v[4 * u + 1], w01, sv);
                sv = fmaf(v[4 * u + 2], w10, sv);
                sv = fmaf(v[4 * u + 3], w11, sv);
                s[u] = sv;
            }
#pragma unroll
            for (int p2 = 0; p2 < 2; p2++) {
                unsigned hi, lo;
                split_pair(s[2 * p2], s[2 * p2 + 1], hi, lo);
                sts32(arow_hi + (c0 + 2 * p2) * 2, hi);
                sts32(arow_lo + (c0 + 2 * p2) * 2, lo);
            }
        }

        __syncthreads();

        // ---- warp GEMM via ldmatrix: 32 px x 64 out, K=64, 3 terms ----
#pragma unroll
        for (int ks = 0; ks < 4; ks++) {
            unsigned kb = ks * 32;
            unsigned ahi[2][4], alo[2][4];
#pragma unroll
            for (int mt = 0; mt < 2; mt++) {
                ldsm_x4(ahi[mt], sb + SA_HI + afrag + mt * 16 * ROWB + kb);
                ldsm_x4(alo[mt], sb + SA_LO + afrag + mt * 16 * ROWB + kb);
            }
#pragma unroll
            for (int p = 0; p < 4; p++) {
                unsigned bh4[4], bl4[4];
                ldsm_x4(bh4, sb + SB_HI + p * 16 * ROWB + bfrag + kb);
                ldsm_x4(bl4, sb + K3_SB_LO + p * 16 * ROWB + bfrag + kb);
#pragma unroll
                for (int mt = 0; mt < 2; mt++) {
                    mma16816(d[mt][2 * p],     ahi[mt], bh4[0], bh4[1]);
                    mma16816(d[mt][2 * p],     ahi[mt], bl4[0], bl4[1]);
                    mma16816(d[mt][2 * p],     alo[mt], bh4[0], bh4[1]);
                    mma16816(d[mt][2 * p + 1], ahi[mt], bh4[2], bh4[3]);
                    mma16816(d[mt][2 * p + 1], ahi[mt], bl4[2], bl4[3]);
                    mma16816(d[mt][2 * p + 1], alo[mt], bh4[2], bh4[3]);
                }
            }
        }
    }

#pragma unroll
    for (int mt = 0; mt < 2; mt++) {
#pragma unroll
        for (int nt = 0; nt < 8; nt++) {
            int px0 = warp * 32 + mt * 16 + gid;
            int o0  = nt * 8 + tig * 2;
            float* op = out + ((size_t)b * 64 + o0) * HW + hw_base;
            op[px0]           = d[mt][nt][0];
            op[HW + px0]      = d[mt][nt][1];
            op[px0 + 8]       = d[mt][nt][2];
            op[HW + px0 + 8]  = d[mt][nt][3];
        }
    }
}

// ===========================================================================
extern "C" void kernel_launch(void* const* d_in, const int* in_sizes, int n_in,
                              void* d_out, int out_size) {
    const float* x_img  = (const float*)d_in[0];
    const float* x_cont = (const float*)d_in[1];
    const float* w_fuse = (const float*)d_in[2];
    const float* w_off  = (const float*)d_in[3];
    const float* b_off  = (const float*)d_in[4];
    const float* w_mod  = (const float*)d_in[5];
    const float* b_mod  = (const float*)d_in[6];
    const float* w_reg  = (const float*)d_in[7];
    float* out = (float*)d_out;

    cudaFuncSetAttribute(k1_fuse,
                         cudaFuncAttributeMaxDynamicSharedMemorySize, K1_SMEM);
    cudaFuncSetAttribute(k2_offmod,
                         cudaFuncAttributeMaxDynamicSharedMemorySize, K2_SMEM);
    cudaFuncSetAttribute(k3_deform,
                         cudaFuncAttributeMaxDynamicSharedMemorySize, K3_SMEM);

    ksetup<<<128, 256>>>(w_fuse, w_off, w_mod, w_reg);
    // all: 1024 blocks x 128 thr; CTA = 128-px tile
    k1_fuse<<<1024, 128, K1_SMEM>>>(x_img, x_cont);
    k2_offmod<<<1024, 128, K2_SMEM>>>(b_off, b_mod);
    k3_deform<<<1024, 128, K3_SMEM>>>(out);
}